// round 8
// baseline (speedup 1.0000x reference)
#include <cuda_runtime.h>
#include <cstdint>

#define TT   16384
#define ED   1024
#define HD   1024
#define G4   4096
#define NMV  128        // matvec CTAs (each owns 8 h-indices = 32 gate rows)
#define NLOSS 16        // dedicated loss CTAs
#define RTHREADS 512

// ---- scratch (static device memory; no allocations anywhere) ----
__device__ float        g_xg[TT][G4];       // 256 MB: input projections
__device__ float        g_hbuf[TT][HD];     // 64 MB: h history (loss copy)
__device__ float        g_hrep[4][TT][HD];  // 256 MB: h replicas for matvec fetch
__device__ unsigned int g_flag[NMV][8];     // per-CTA monotonic step flags (32B stride)
__device__ float        g_loss[TT];         // per-step losses
__device__ int          g_ys[TT];           // normalized labels (int32)

// ---- helpers ----
__device__ __forceinline__ unsigned long long ffma2(unsigned long long a,
                                                    unsigned long long b,
                                                    unsigned long long c) {
    unsigned long long d;
    asm("fma.rn.f32x2 %0, %1, %2, %3;" : "=l"(d) : "l"(a), "l"(b), "l"(c));
    return d;
}
__device__ __forceinline__ float2 unpk(unsigned long long v) {
    float2 r;
    asm("mov.b64 {%0, %1}, %2;" : "=f"(r.x), "=f"(r.y) : "l"(v));
    return r;
}
__device__ __forceinline__ unsigned long long pk2(float lo, float hi) {
    unsigned long long v;
    asm("mov.b64 %0, {%1, %2};" : "=l"(v) : "f"(lo), "f"(hi));
    return v;
}
__device__ __forceinline__ unsigned int ld_acq(const unsigned int* p) {
    unsigned int v;
    asm volatile("ld.acquire.gpu.global.u32 %0, [%1];" : "=r"(v) : "l"(p) : "memory");
    return v;
}
__device__ __forceinline__ void st_rel_u32(unsigned int* p, unsigned int v) {
    asm volatile("st.release.gpu.global.u32 [%0], %1;" :: "l"(p), "r"(v) : "memory");
}
__device__ __forceinline__ float ex2f(float x) {
    float y; asm("ex2.approx.f32 %0, %1;" : "=f"(y) : "f"(x)); return y;
}
__device__ __forceinline__ float rcpf(float x) {
    float y; asm("rcp.approx.f32 %0, %1;" : "=f"(y) : "f"(x)); return y;
}
#define L2E 1.4426950408889634f
__device__ __forceinline__ float sigm(float x) {           // 1/(1+e^-x)
    return rcpf(1.f + ex2f(-x * L2E));
}
__device__ __forceinline__ float tanha(float x) {          // 1 - 2/(e^{2x}+1)
    return fmaf(-2.f, rcpf(1.f + ex2f(x * (2.f * L2E))), 1.f);
}
// warp-collective: wait until ALL 128 CTA flags >= tgt (call from ONE warp)
__device__ __forceinline__ void wait_flags(int lane, unsigned int tgt) {
    const unsigned int* f0 = &g_flag[4 * lane + 0][0];
    const unsigned int* f1 = &g_flag[4 * lane + 1][0];
    const unsigned int* f2 = &g_flag[4 * lane + 2][0];
    const unsigned int* f3 = &g_flag[4 * lane + 3][0];
    for (;;) {
        unsigned int a = ld_acq(f0);   // all 4 flags on ONE 128B line (lane-private)
        unsigned int b = ld_acq(f1);
        unsigned int c = ld_acq(f2);
        unsigned int d = ld_acq(f3);
        bool ok = (a >= tgt) & (b >= tgt) & (c >= tgt) & (d >= tgt);
        if (__all_sync(0xffffffffu, ok)) break;
    }
}

// ---- kernel 0: reset flags + normalize ys dtype (int64 vs int32 autodetect) ----
__global__ void __launch_bounds__(256) reset_k(const int* __restrict__ ysr) {
    int i = blockIdx.x * blockDim.x + threadIdx.x;
    bool is64 = true;
#pragma unroll
    for (int q = 1; q < 16; q += 2) is64 = is64 && (ysr[q] == 0);
    if (i < TT) g_ys[i] = is64 ? ysr[2 * i] : ysr[i];
    if (i < NMV * 8) (&g_flag[0][0])[i] = 0u;
}

// ---- kernel 1: xg = Xs @ W_ih^T + (b_ih + b_hh), packed-f32x2 tiled GEMM ----
__global__ void __launch_bounds__(256) gemm_xg(const float* __restrict__ X,
                                               const float* __restrict__ W,
                                               const float* __restrict__ bih,
                                               const float* __restrict__ bhh) {
    __shared__ float As[8][128];
    __shared__ float Bs[8][128];
    const int tid = threadIdx.x;
    const int tx = tid & 15, ty = tid >> 4;
    const int bm = blockIdx.y * 128;
    const int bn = blockIdx.x * 128;
    const int lr = tid >> 1;            // 0..127
    const int lc = (tid & 1) << 2;      // 0 or 4
    const float* Ag = X + (size_t)(bm + lr) * ED + lc;
    const float* Bg = W + (size_t)(bn + lr) * ED + lc;

    unsigned long long acc2[8][4];
#pragma unroll
    for (int i = 0; i < 8; i++)
#pragma unroll
        for (int j = 0; j < 4; j++) acc2[i][j] = 0ull;

    for (int k0 = 0; k0 < ED; k0 += 8) {
        float4 av = *(const float4*)(Ag + k0);
        float4 bv = *(const float4*)(Bg + k0);
        __syncthreads();   // previous iteration's reads complete
        As[lc + 0][lr] = av.x; As[lc + 1][lr] = av.y;
        As[lc + 2][lr] = av.z; As[lc + 3][lr] = av.w;
        Bs[lc + 0][lr] = bv.x; Bs[lc + 1][lr] = bv.y;
        Bs[lc + 2][lr] = bv.z; Bs[lc + 3][lr] = bv.w;
        __syncthreads();
#pragma unroll
        for (int kk = 0; kk < 8; kk++) {
            float a[8];
            *(float4*)(a)     = *(const float4*)&As[kk][ty * 8];
            *(float4*)(a + 4) = *(const float4*)&As[kk][ty * 8 + 4];
            ulonglong2 b01 = *(const ulonglong2*)&Bs[kk][tx * 8];
            ulonglong2 b23 = *(const ulonglong2*)&Bs[kk][tx * 8 + 4];
#pragma unroll
            for (int i = 0; i < 8; i++) {
                unsigned long long ad = pk2(a[i], a[i]);
                acc2[i][0] = ffma2(ad, b01.x, acc2[i][0]);
                acc2[i][1] = ffma2(ad, b01.y, acc2[i][1]);
                acc2[i][2] = ffma2(ad, b23.x, acc2[i][2]);
                acc2[i][3] = ffma2(ad, b23.y, acc2[i][3]);
            }
        }
    }

    const int n0 = bn + tx * 8;
    float bias[8];
#pragma unroll
    for (int j = 0; j < 8; j++) bias[j] = bih[n0 + j] + bhh[n0 + j];
#pragma unroll
    for (int i = 0; i < 8; i++) {
        const int m = bm + ty * 8 + i;
        float2 c0 = unpk(acc2[i][0]), c1 = unpk(acc2[i][1]);
        float2 c2 = unpk(acc2[i][2]), c3 = unpk(acc2[i][3]);
        float4 o0 = make_float4(c0.x + bias[0], c0.y + bias[1],
                                c1.x + bias[2], c1.y + bias[3]);
        float4 o1 = make_float4(c2.x + bias[4], c2.y + bias[5],
                                c3.x + bias[6], c3.y + bias[7]);
        *(float4*)&g_xg[m][n0]     = o0;
        *(float4*)&g_xg[m][n0 + 4] = o1;
    }
}

// ---- kernel 2: persistent LSTM recurrence + loss ----
// Publish: each CTA stores its OWN flag word = t+1 (NO atomics -> no LTS
// serialization; the 128 publishes complete in parallel).
// Detect: warp0 only (lane l checks 4 flags on its private line), then ONE
// __syncthreads fanout. Total polling warps = 128 (proven benign).
__global__ void __launch_bounds__(RTHREADS, 1) lstm_persist(const float* __restrict__ Whh) {
    const int b   = blockIdx.x;
    const int tid = threadIdx.x;

    if (b < NMV) {
        __shared__ float part[16][32];
        const int w = tid >> 5, l = tid & 31;
        // lane l -> gate (l>>3) in {i,f,g,o}, local row j = l&7; global j = 8b+(l&7)
        const int row = ((l >> 3) << 10) + (b << 3) + (l & 7);

        // This thread's 64 W_hh values in registers (cols 64w .. 64w+63).
        ulonglong2 Wr[16];
        {
            const ulonglong2* wp =
                (const ulonglong2*)(Whh + (size_t)row * HD + (w << 6));
#pragma unroll
            for (int q = 0; q < 16; q++) Wr[q] = wp[q];
        }
        float cstate = 0.f;              // warp0: replicated across 8-lane groups
        float xcur = 0.f;
        if (w == 0) xcur = g_xg[0][row];
        const int rep = b & 3;

        for (int t = 0; t < TT; t++) {
            if (t > 0) {
                if (w == 0) wait_flags(l, (unsigned int)t);   // all flags >= t
                __syncthreads();         // fan out: h_{t-1} visible
            }
            float psum = 0.f;
            if (t > 0) {
                const ulonglong2* hp =
                    (const ulonglong2*)(&g_hrep[rep][t - 1][w << 6]);
                unsigned long long a0 = 0ull, a1 = 0ull;
#pragma unroll
                for (int q = 0; q < 16; q++) {
                    ulonglong2 hh = hp[q];           // LDG.128, warp-uniform addr
                    a0 = ffma2(Wr[q].x, hh.x, a0);
                    a1 = ffma2(Wr[q].y, hh.y, a1);
                }
                float2 p0 = unpk(a0), p1 = unpk(a1);
                psum = (p0.x + p1.x) + (p0.y + p1.y);
            }
            part[w][l] = psum;
            __syncthreads();  // partials of step t visible to warp0

            if (w == 0) {
                float s0 = part[0][l]  + part[1][l];
                float s1 = part[2][l]  + part[3][l];
                float s2 = part[4][l]  + part[5][l];
                float s3 = part[6][l]  + part[7][l];
                float s4 = part[8][l]  + part[9][l];
                float s5 = part[10][l] + part[11][l];
                float s6 = part[12][l] + part[13][l];
                float s7 = part[14][l] + part[15][l];
                float u0 = (s0 + s1) + (s2 + s3);
                float u1 = (s4 + s5) + (s6 + s7);
                float gpre = xcur + (u0 + u1);

                // lane-parallel activations: gates i,f,o -> sigmoid; g -> tanh
                float act = ((l >> 3) == 2) ? tanha(gpre) : sigm(gpre);

                const int jj = l & 7;
                float ig = __shfl_sync(0xffffffffu, act, jj);
                float fg = __shfl_sync(0xffffffffu, act, jj + 8);
                float gg = __shfl_sync(0xffffffffu, act, jj + 16);
                float og = __shfl_sync(0xffffffffu, act, jj + 24);
                // every lane carries cstate/hv of row (l&7) -> identical per group
                cstate = fmaf(fg, cstate, ig * gg);
                float hv = og * tanha(cstate);
                const int idx = (b << 3) + jj;
                g_hrep[l >> 3][t][idx] = hv;        // ONE STG covers 4 replicas
                if (l < 8) g_hbuf[t][idx] = hv;     // loss copy
                __syncwarp();
                if (l == 0) st_rel_u32(&g_flag[b][0], (unsigned int)(t + 1));
                if (t + 1 < TT) xcur = g_xg[t + 1][row];  // prefetch, off path
            }
        }
    } else {
        // ---- loss CTA (warp0-only flag poll; off the critical path) ----
        __shared__ float sred[RTHREADS];
        const int lcta = b - NMV;
        for (int t = lcta; t < TT; t += NLOSS) {
            if (tid < 32) wait_flags(tid, (unsigned int)(t + 1));
            __syncthreads();
            float v0 = g_hbuf[t][2 * tid];
            float v1 = g_hbuf[t][2 * tid + 1];
            sred[tid] = ex2f(v0 * L2E) + ex2f(v1 * L2E);
            __syncthreads();
            for (int s = RTHREADS / 2; s >= 32; s >>= 1) {
                if (tid < s) sred[tid] += sred[tid + s];
                __syncthreads();
            }
            if (tid < 32) {
                float v = sred[tid];
                v += __shfl_down_sync(0xffffffffu, v, 16);
                v += __shfl_down_sync(0xffffffffu, v, 8);
                v += __shfl_down_sync(0xffffffffu, v, 4);
                v += __shfl_down_sync(0xffffffffu, v, 2);
                v += __shfl_down_sync(0xffffffffu, v, 1);
                if (tid == 0) {
                    int y = g_ys[t];
                    g_loss[t] = __logf(v) - g_hbuf[t][y];  // h in (-1,1): no max shift
                }
            }
            __syncthreads();
        }
    }
}

// ---- kernel 3: deterministic final sum ----
__global__ void __launch_bounds__(256) finalize_k(float* __restrict__ out) {
    __shared__ float sr[256];
    const int tid = threadIdx.x;
    float s = 0.f;
    for (int i = tid; i < TT; i += 256) s += g_loss[i];
    sr[tid] = s;
    __syncthreads();
    for (int st = 128; st >= 1; st >>= 1) {
        if (tid < st) sr[tid] += sr[tid + st];
        __syncthreads();
    }
    if (tid == 0) out[0] = sr[0];
}

// ---- entry point ----
extern "C" void kernel_launch(void* const* d_in, const int* in_sizes, int n_in,
                              void* d_out, int out_size) {
    const float* Xs  = (const float*)d_in[0];
    const float* Wih = (const float*)d_in[1];
    const float* Whh = (const float*)d_in[2];
    const float* bih = (const float*)d_in[3];
    const float* bhh = (const float*)d_in[4];
    const int*   ysr = (const int*)d_in[5];

    reset_k<<<TT / 256, 256>>>(ysr);
    gemm_xg<<<dim3(G4 / 128, TT / 128), 256>>>(Xs, Wih, bih, bhh);
    lstm_persist<<<NMV + NLOSS, RTHREADS>>>(Whh);
    finalize_k<<<1, 256>>>((float*)d_out);
}

// round 9
// speedup vs baseline: 2.0206x; 2.0206x over previous
#include <cuda_runtime.h>
#include <cstdint>

#define TT   16384
#define ED   1024
#define HD   1024
#define G4   4096
#define NMV  128        // matvec CTAs (each owns 8 h-indices = 32 gate rows)
#define NLOSS 16        // dedicated loss CTAs
#define RTHREADS 512

// ---- scratch (static device memory; no allocations anywhere) ----
__device__ float        g_xg[TT][G4];       // 256 MB: input projections
__device__ float        g_hrep[4][TT][HD];  // 256 MB: h replicas (rep0 also feeds loss)
__device__ unsigned int g_cnt[TT][32];      // 2 MB: per-step counters, ONE PER 128B LINE
__device__ float        g_loss[TT];         // per-step losses
__device__ int          g_ys[TT];           // normalized labels (int32)

// ---- helpers ----
__device__ __forceinline__ unsigned long long ffma2(unsigned long long a,
                                                    unsigned long long b,
                                                    unsigned long long c) {
    unsigned long long d;
    asm("fma.rn.f32x2 %0, %1, %2, %3;" : "=l"(d) : "l"(a), "l"(b), "l"(c));
    return d;
}
__device__ __forceinline__ float2 unpk(unsigned long long v) {
    float2 r;
    asm("mov.b64 {%0, %1}, %2;" : "=f"(r.x), "=f"(r.y) : "l"(v));
    return r;
}
__device__ __forceinline__ unsigned long long pk2(float lo, float hi) {
    unsigned long long v;
    asm("mov.b64 %0, {%1, %2};" : "=l"(v) : "f"(lo), "f"(hi));
    return v;
}
__device__ __forceinline__ unsigned int ld_acq(const unsigned int* p) {
    unsigned int v;
    asm volatile("ld.acquire.gpu.global.u32 %0, [%1];" : "=r"(v) : "l"(p) : "memory");
    return v;
}
__device__ __forceinline__ unsigned int ld_rlx(const unsigned int* p) {
    unsigned int v;
    asm volatile("ld.relaxed.gpu.global.u32 %0, [%1];" : "=r"(v) : "l"(p) : "memory");
    return v;
}
__device__ __forceinline__ void red_rel(unsigned int* p) {
    asm volatile("red.release.gpu.global.add.u32 [%0], 1;" :: "l"(p) : "memory");
}
// tid0-only wait: counts <=128 are 7-bit, so OR>=NMV <=> any sample ==NMV
__device__ __forceinline__ void wait_cnt(const unsigned int* p) {
    for (;;) {
        unsigned int a = ld_rlx(p);
        unsigned int b = ld_rlx(p);
        unsigned int c = ld_rlx(p);
        unsigned int d = ld_rlx(p);
        if ((a | b | c | d) >= NMV) break;
    }
    (void)ld_acq(p);   // acquire ordering for subsequent h reads
}
__device__ __forceinline__ float ex2f(float x) {
    float y; asm("ex2.approx.f32 %0, %1;" : "=f"(y) : "f"(x)); return y;
}
__device__ __forceinline__ float rcpf(float x) {
    float y; asm("rcp.approx.f32 %0, %1;" : "=f"(y) : "f"(x)); return y;
}
#define L2E 1.4426950408889634f
__device__ __forceinline__ float sigm(float x) {           // 1/(1+e^-x)
    return rcpf(1.f + ex2f(-x * L2E));
}
__device__ __forceinline__ float tanha(float x) {          // 1 - 2/(e^{2x}+1)
    return fmaf(-2.f, rcpf(1.f + ex2f(x * (2.f * L2E))), 1.f);
}

// ---- kernel 0: reset padded counters ----
__global__ void __launch_bounds__(256) reset_cnt() {
    (&g_cnt[0][0])[blockIdx.x * 256 + threadIdx.x] = 0u;   // TT*32 words
}
// ---- kernel 0b: normalize ys dtype (int64 vs int32 autodetect) ----
__global__ void __launch_bounds__(256) reset_ys(const int* __restrict__ ysr) {
    int i = blockIdx.x * 256 + threadIdx.x;
    bool is64 = true;
#pragma unroll
    for (int q = 1; q < 16; q += 2) is64 = is64 && (ysr[q] == 0);
    if (i < TT) g_ys[i] = is64 ? ysr[2 * i] : ysr[i];
}

// ---- kernel 1: xg = Xs @ W_ih^T + (b_ih + b_hh), pipelined f32x2 GEMM ----
// 128x128 tile, BK=8, 256 threads; next slab's global loads issued BEFORE the
// compute block so L2 latency overlaps the 256 FFMA2s per thread per iter.
__global__ void __launch_bounds__(256) gemm_xg(const float* __restrict__ X,
                                               const float* __restrict__ W,
                                               const float* __restrict__ bih,
                                               const float* __restrict__ bhh) {
    __shared__ float As[8][128];
    __shared__ float Bs[8][128];
    const int tid = threadIdx.x;
    const int tx = tid & 15, ty = tid >> 4;
    const int bm = blockIdx.y * 128;
    const int bn = blockIdx.x * 128;
    const int lr = tid >> 1;            // 0..127
    const int lc = (tid & 1) << 2;      // 0 or 4
    const float* Ag = X + (size_t)(bm + lr) * ED + lc;
    const float* Bg = W + (size_t)(bn + lr) * ED + lc;

    unsigned long long acc2[8][4];
#pragma unroll
    for (int i = 0; i < 8; i++)
#pragma unroll
        for (int j = 0; j < 4; j++) acc2[i][j] = 0ull;

    float4 av = *(const float4*)(Ag);
    float4 bv = *(const float4*)(Bg);
    for (int k0 = 0; k0 < ED; k0 += 8) {
        __syncthreads();   // previous compute done reading smem
        As[lc + 0][lr] = av.x; As[lc + 1][lr] = av.y;
        As[lc + 2][lr] = av.z; As[lc + 3][lr] = av.w;
        Bs[lc + 0][lr] = bv.x; Bs[lc + 1][lr] = bv.y;
        Bs[lc + 2][lr] = bv.z; Bs[lc + 3][lr] = bv.w;
        __syncthreads();
        if (k0 + 8 < ED) {                     // prefetch next slab NOW
            av = *(const float4*)(Ag + k0 + 8);
            bv = *(const float4*)(Bg + k0 + 8);
        }
#pragma unroll
        for (int kk = 0; kk < 8; kk++) {
            float a[8];
            *(float4*)(a)     = *(const float4*)&As[kk][ty * 8];
            *(float4*)(a + 4) = *(const float4*)&As[kk][ty * 8 + 4];
            ulonglong2 b01 = *(const ulonglong2*)&Bs[kk][tx * 8];
            ulonglong2 b23 = *(const ulonglong2*)&Bs[kk][tx * 8 + 4];
#pragma unroll
            for (int i = 0; i < 8; i++) {
                unsigned long long ad = pk2(a[i], a[i]);
                acc2[i][0] = ffma2(ad, b01.x, acc2[i][0]);
                acc2[i][1] = ffma2(ad, b01.y, acc2[i][1]);
                acc2[i][2] = ffma2(ad, b23.x, acc2[i][2]);
                acc2[i][3] = ffma2(ad, b23.y, acc2[i][3]);
            }
        }
    }

    const int n0 = bn + tx * 8;
    float bias[8];
#pragma unroll
    for (int j = 0; j < 8; j++) bias[j] = bih[n0 + j] + bhh[n0 + j];
#pragma unroll
    for (int i = 0; i < 8; i++) {
        const int m = bm + ty * 8 + i;
        float2 c0 = unpk(acc2[i][0]), c1 = unpk(acc2[i][1]);
        float2 c2 = unpk(acc2[i][2]), c3 = unpk(acc2[i][3]);
        float4 o0 = make_float4(c0.x + bias[0], c0.y + bias[1],
                                c1.x + bias[2], c1.y + bias[3]);
        float4 o1 = make_float4(c2.x + bias[4], c2.y + bias[5],
                                c3.x + bias[6], c3.y + bias[7]);
        *(float4*)&g_xg[m][n0]     = o0;
        *(float4*)&g_xg[m][n0 + 4] = o1;
    }
}

// ---- kernel 2: persistent LSTM recurrence + loss ----
// Proven R5 skeleton: tid0 poll one word + bar fanout; direct per-warp h LDG
// from replica (b&3); lane-trick publish (one STG covers 4 replicas).
// New: counters padded to 1/line; xg prefetch hoisted; no separate loss copy.
__global__ void __launch_bounds__(RTHREADS, 1) lstm_persist(const float* __restrict__ Whh) {
    const int b   = blockIdx.x;
    const int tid = threadIdx.x;

    if (b < NMV) {
        __shared__ float part[16][32];
        const int w = tid >> 5, l = tid & 31;
        // lane l -> gate (l>>3) in {i,f,g,o}, local row j = l&7; global j = 8b+(l&7)
        const int row = ((l >> 3) << 10) + (b << 3) + (l & 7);

        // This thread's 64 W_hh values in registers (cols 64w .. 64w+63).
        ulonglong2 Wr[16];
        {
            const ulonglong2* wp =
                (const ulonglong2*)(Whh + (size_t)row * HD + (w << 6));
#pragma unroll
            for (int q = 0; q < 16; q++) Wr[q] = wp[q];
        }
        float cstate = 0.f;              // warp0: replicated across 8-lane groups
        float xcur = 0.f;
        if (w == 0) xcur = g_xg[0][row];
        const int rep = b & 3;

        for (int t = 0; t < TT; t++) {
            if (t > 0) {
                if (tid == 0) wait_cnt(&g_cnt[t - 1][0]);
                __syncthreads();         // fan out: h_{t-1} visible
            }
            float psum = 0.f;
            if (t > 0) {
                const ulonglong2* hp =
                    (const ulonglong2*)(&g_hrep[rep][t - 1][w << 6]);
                unsigned long long a0 = 0ull, a1 = 0ull;
#pragma unroll
                for (int q = 0; q < 16; q++) {
                    ulonglong2 hh = hp[q];           // LDG.128, warp-uniform addr
                    a0 = ffma2(Wr[q].x, hh.x, a0);
                    a1 = ffma2(Wr[q].y, hh.y, a1);
                }
                float2 p0 = unpk(a0), p1 = unpk(a1);
                psum = (p0.x + p1.x) + (p0.y + p1.y);
            }
            part[w][l] = psum;
            __syncthreads();  // partials of step t visible to warp0

            if (w == 0) {
                float s0 = part[0][l]  + part[1][l];
                float s1 = part[2][l]  + part[3][l];
                float s2 = part[4][l]  + part[5][l];
                float s3 = part[6][l]  + part[7][l];
                float s4 = part[8][l]  + part[9][l];
                float s5 = part[10][l] + part[11][l];
                float s6 = part[12][l] + part[13][l];
                float s7 = part[14][l] + part[15][l];
                float u0 = (s0 + s1) + (s2 + s3);
                float u1 = (s4 + s5) + (s6 + s7);
                float gpre = xcur + (u0 + u1);

                // xcur consumed -> issue next step's DRAM prefetch IMMEDIATELY
                if (t + 1 < TT) xcur = g_xg[t + 1][row];

                // lane-parallel activations: gates i,f,o -> sigmoid; g -> tanh
                float act = ((l >> 3) == 2) ? tanha(gpre) : sigm(gpre);

                const int jj = l & 7;
                float ig = __shfl_sync(0xffffffffu, act, jj);
                float fg = __shfl_sync(0xffffffffu, act, jj + 8);
                float gg = __shfl_sync(0xffffffffu, act, jj + 16);
                float og = __shfl_sync(0xffffffffu, act, jj + 24);
                // every lane carries cstate/hv of row (l&7) -> identical per group
                cstate = fmaf(fg, cstate, ig * gg);
                float hv = og * tanha(cstate);
                g_hrep[l >> 3][t][(b << 3) + jj] = hv;   // ONE STG: 4 replicas
                __syncwarp();
                if (l == 0) red_rel(&g_cnt[t][0]);       // publish (release)
            }
        }
    } else {
        // ---- loss CTA (reads replica 0; off the critical path) ----
        __shared__ float sred[RTHREADS];
        const int lcta = b - NMV;
        for (int t = lcta; t < TT; t += NLOSS) {
            if (tid == 0) wait_cnt(&g_cnt[t][0]);
            __syncthreads();
            float v0 = g_hrep[0][t][2 * tid];
            float v1 = g_hrep[0][t][2 * tid + 1];
            sred[tid] = ex2f(v0 * L2E) + ex2f(v1 * L2E);
            __syncthreads();
            for (int s = RTHREADS / 2; s >= 32; s >>= 1) {
                if (tid < s) sred[tid] += sred[tid + s];
                __syncthreads();
            }
            if (tid < 32) {
                float v = sred[tid];
                v += __shfl_down_sync(0xffffffffu, v, 16);
                v += __shfl_down_sync(0xffffffffu, v, 8);
                v += __shfl_down_sync(0xffffffffu, v, 4);
                v += __shfl_down_sync(0xffffffffu, v, 2);
                v += __shfl_down_sync(0xffffffffu, v, 1);
                if (tid == 0) {
                    int y = g_ys[t];
                    g_loss[t] = __logf(v) - g_hrep[0][t][y];  // h in (-1,1)
                }
            }
            __syncthreads();
        }
    }
}

// ---- kernel 3: deterministic final sum ----
__global__ void __launch_bounds__(256) finalize_k(float* __restrict__ out) {
    __shared__ float sr[256];
    const int tid = threadIdx.x;
    float s = 0.f;
    for (int i = tid; i < TT; i += 256) s += g_loss[i];
    sr[tid] = s;
    __syncthreads();
    for (int st = 128; st >= 1; st >>= 1) {
        if (tid < st) sr[tid] += sr[tid + st];
        __syncthreads();
    }
    if (tid == 0) out[0] = sr[0];
}

// ---- entry point ----
extern "C" void kernel_launch(void* const* d_in, const int* in_sizes, int n_in,
                              void* d_out, int out_size) {
    const float* Xs  = (const float*)d_in[0];
    const float* Wih = (const float*)d_in[1];
    const float* Whh = (const float*)d_in[2];
    const float* bih = (const float*)d_in[3];
    const float* bhh = (const float*)d_in[4];
    const int*   ysr = (const int*)d_in[5];

    reset_cnt<<<(TT * 32) / 256, 256>>>();
    reset_ys<<<TT / 256, 256>>>(ysr);
    gemm_xg<<<dim3(G4 / 128, TT / 128), 256>>>(Xs, Wih, bih, bhh);
    lstm_persist<<<NMV + NLOSS, RTHREADS>>>(Whh);
    finalize_k<<<1, 256>>>((float*)d_out);
}